// round 2
// baseline (speedup 1.0000x reference)
#include <cuda_runtime.h>
#include <math.h>

// Problem constants (fixed by the dataset)
#define BB 2
#define LL 2048
#define DD 2048
#define HH 16
#define HD 128
#define MROWS (BB * LL)   // 4096

// ---------------------------------------------------------------------------
// Scratch (no cudaMalloc allowed — __device__ globals per the rules)
// ---------------------------------------------------------------------------
__device__ float g_q[(size_t)MROWS * DD];
__device__ float g_k[(size_t)MROWS * DD];
__device__ float g_v[(size_t)MROWS * DD];
__device__ float g_att[(size_t)MROWS * DD];

// ---------------------------------------------------------------------------
// GEMM: C[M,N] = A[M,K] * B[N,K]^T   (both row-major, K contiguous — NT GEMM)
// 128x128 block tile, BK=16, 256 threads, 8x8 micro-tile.
// ---------------------------------------------------------------------------
#define GBM 128
#define GBN 128
#define GBK 16

__global__ __launch_bounds__(256, 2)
void gemm_nt_kernel(const float* __restrict__ A, const float* __restrict__ B,
                    float* __restrict__ C, int M, int N, int K) {
    __shared__ float As[GBK][GBM + 4];
    __shared__ float Bs[GBK][GBN + 4];

    const int tid = threadIdx.x;          // 0..255
    const int tx = tid % 16;              // col group
    const int ty = tid / 16;              // row group
    const int bm = blockIdx.y * GBM;
    const int bn = blockIdx.x * GBN;

    // global-load mapping: 128 rows x 4 float4 per matrix = 512 float4 / 256 thr
    const int lr = tid / 4;               // 0..63
    const int lc = (tid % 4) * 4;         // 0,4,8,12

    float acc[8][8];
#pragma unroll
    for (int i = 0; i < 8; i++)
#pragma unroll
        for (int j = 0; j < 8; j++) acc[i][j] = 0.f;

    for (int k0 = 0; k0 < K; k0 += GBK) {
#pragma unroll
        for (int h = 0; h < 2; h++) {
            int row = lr + h * 64;
            float4 va = *reinterpret_cast<const float4*>(
                &A[(size_t)(bm + row) * K + k0 + lc]);
            As[lc + 0][row] = va.x; As[lc + 1][row] = va.y;
            As[lc + 2][row] = va.z; As[lc + 3][row] = va.w;
            float4 vb = *reinterpret_cast<const float4*>(
                &B[(size_t)(bn + row) * K + k0 + lc]);
            Bs[lc + 0][row] = vb.x; Bs[lc + 1][row] = vb.y;
            Bs[lc + 2][row] = vb.z; Bs[lc + 3][row] = vb.w;
        }
        __syncthreads();

#pragma unroll
        for (int kk = 0; kk < GBK; kk++) {
            float4 a0 = *reinterpret_cast<const float4*>(&As[kk][ty * 4]);
            float4 a1 = *reinterpret_cast<const float4*>(&As[kk][64 + ty * 4]);
            float4 b0 = *reinterpret_cast<const float4*>(&Bs[kk][tx * 4]);
            float4 b1 = *reinterpret_cast<const float4*>(&Bs[kk][64 + tx * 4]);
            float a[8] = {a0.x, a0.y, a0.z, a0.w, a1.x, a1.y, a1.z, a1.w};
            float b[8] = {b0.x, b0.y, b0.z, b0.w, b1.x, b1.y, b1.z, b1.w};
#pragma unroll
            for (int i = 0; i < 8; i++)
#pragma unroll
                for (int j = 0; j < 8; j++) acc[i][j] += a[i] * b[j];
        }
        __syncthreads();
    }

#pragma unroll
    for (int i = 0; i < 8; i++) {
        int row = bm + ((i < 4) ? (ty * 4 + i) : (64 + ty * 4 + (i - 4)));
        float4 c0 = make_float4(acc[i][0], acc[i][1], acc[i][2], acc[i][3]);
        float4 c1 = make_float4(acc[i][4], acc[i][5], acc[i][6], acc[i][7]);
        *reinterpret_cast<float4*>(&C[(size_t)row * N + bn + tx * 4]) = c0;
        *reinterpret_cast<float4*>(&C[(size_t)row * N + bn + 64 + tx * 4]) = c1;
    }
}

// ---------------------------------------------------------------------------
// RoPE (in-place on [B*L, H, HD] tensor). One thread per (row, head, i<64).
// ---------------------------------------------------------------------------
__global__ void rope_kernel(float* __restrict__ t) {
    int idx = blockIdx.x * blockDim.x + threadIdx.x;
    const int total = MROWS * HH * 64;
    if (idx >= total) return;
    int i = idx % 64;
    int h = (idx / 64) % HH;
    int row = idx / (64 * HH);     // b*L + l
    int pos = row % LL;

    // inv_freq = 10000^(-i/64)
    const float LN10000_DIV64 = 0.14391156f;  // ln(10000)/64
    float freq = expf(-(float)i * LN10000_DIV64);
    float ang = (float)pos * freq;
    float s, c;
    sincosf(ang, &s, &c);

    float* p = t + (size_t)row * DD + h * HD;
    float a = p[i];
    float b = p[i + 64];
    p[i]      = a * c - b * s;
    p[i + 64] = b * c + a * s;
}

// ---------------------------------------------------------------------------
// Flash attention, fp32, streaming softmax. BM=BN=64, 256 threads.
// Layout: q/k/v/o are [B*L, H, HD] (row stride D=2048 floats).
// ---------------------------------------------------------------------------
#define FBM 64
#define FBN 64
#define QSTRIDE 132   // HD + 4 padding
#define SSTRIDE 68    // FBN + 4 padding (keeps 16B alignment)

__global__ __launch_bounds__(256, 1)
void flash_kernel(const float* __restrict__ q, const float* __restrict__ k,
                  const float* __restrict__ v, float* __restrict__ o) {
    extern __shared__ float sm[];
    float* Qs   = sm;                       // [FBM][QSTRIDE]
    float* Ks   = Qs + FBM * QSTRIDE;       // [FBN][QSTRIDE]
    float* Vs   = Ks + FBN * QSTRIDE;       // [FBN][QSTRIDE]
    float* S    = Vs + FBN * QSTRIDE;       // [FBM][SSTRIDE]
    float* mrow = S + FBM * SSTRIDE;        // [FBM]
    float* lrow = mrow + FBM;               // [FBM]
    float* srow = lrow + FBM;               // [FBM]

    const int tid = threadIdx.x;
    const int tx = tid % 16;                // 0..15
    const int ty = tid / 16;                // 0..15
    const int b = blockIdx.z;
    const int h = blockIdx.y;
    const int q0 = blockIdx.x * FBM;

    const size_t rs = (size_t)HH * HD;      // 2048
    const float* qb = q + (size_t)b * LL * rs + (size_t)h * HD;
    const float* kb = k + (size_t)b * LL * rs + (size_t)h * HD;
    const float* vb = v + (size_t)b * LL * rs + (size_t)h * HD;

    // load Q tile (64 x 128)
    for (int i = tid; i < FBM * 32; i += 256) {
        int r = i / 32, c = (i % 32) * 4;
        float4 val = *reinterpret_cast<const float4*>(
            &qb[(size_t)(q0 + r) * rs + c]);
        *reinterpret_cast<float4*>(&Qs[r * QSTRIDE + c]) = val;
    }
    if (tid < FBM) { mrow[tid] = -INFINITY; lrow[tid] = 0.f; }

    float acc[4][8];
#pragma unroll
    for (int i = 0; i < 4; i++)
#pragma unroll
        for (int j = 0; j < 8; j++) acc[i][j] = 0.f;

    __syncthreads();
    const float scale = 0.08838834764831845f;  // 1/sqrt(128)

    for (int k0 = 0; k0 < LL; k0 += FBN) {
        // load K/V tiles
        for (int i = tid; i < FBN * 32; i += 256) {
            int r = i / 32, c = (i % 32) * 4;
            *reinterpret_cast<float4*>(&Ks[r * QSTRIDE + c]) =
                *reinterpret_cast<const float4*>(&kb[(size_t)(k0 + r) * rs + c]);
            *reinterpret_cast<float4*>(&Vs[r * QSTRIDE + c]) =
                *reinterpret_cast<const float4*>(&vb[(size_t)(k0 + r) * rs + c]);
        }
        __syncthreads();

        // S = Q Kt (this thread: rows ty*4+i, cols tx*4+j)
        float sacc[4][4];
#pragma unroll
        for (int i = 0; i < 4; i++)
#pragma unroll
            for (int j = 0; j < 4; j++) sacc[i][j] = 0.f;

        for (int d = 0; d < HD; d += 4) {
            float4 q4[4], k4[4];
#pragma unroll
            for (int i = 0; i < 4; i++)
                q4[i] = *reinterpret_cast<const float4*>(
                    &Qs[(ty * 4 + i) * QSTRIDE + d]);
#pragma unroll
            for (int j = 0; j < 4; j++)
                k4[j] = *reinterpret_cast<const float4*>(
                    &Ks[(tx * 4 + j) * QSTRIDE + d]);
#pragma unroll
            for (int i = 0; i < 4; i++)
#pragma unroll
                for (int j = 0; j < 4; j++) {
                    sacc[i][j] += q4[i].x * k4[j].x;
                    sacc[i][j] += q4[i].y * k4[j].y;
                    sacc[i][j] += q4[i].z * k4[j].z;
                    sacc[i][j] += q4[i].w * k4[j].w;
                }
        }
#pragma unroll
        for (int i = 0; i < 4; i++) {
            float4 sv = make_float4(sacc[i][0] * scale, sacc[i][1] * scale,
                                    sacc[i][2] * scale, sacc[i][3] * scale);
            *reinterpret_cast<float4*>(&S[(ty * 4 + i) * SSTRIDE + tx * 4]) = sv;
        }
        __syncthreads();

        // per-row online softmax (one thread per row)
        if (tid < FBM) {
            float mold = mrow[tid];
            float mt = mold;
            float* srowp = &S[tid * SSTRIDE];
#pragma unroll 8
            for (int j = 0; j < FBN; j++) mt = fmaxf(mt, srowp[j]);
            float sc = __expf(mold - mt);
            float ls = 0.f;
#pragma unroll 8
            for (int j = 0; j < FBN; j++) {
                float p = __expf(srowp[j] - mt);
                srowp[j] = p;
                ls += p;
            }
            mrow[tid] = mt;
            lrow[tid] = lrow[tid] * sc + ls;
            srow[tid] = sc;
        }
        __syncthreads();

        // O = O*scale + P V (this thread: rows ty*4+i, cols tx*8+j)
#pragma unroll
        for (int i = 0; i < 4; i++) {
            float sc = srow[ty * 4 + i];
#pragma unroll
            for (int j = 0; j < 8; j++) acc[i][j] *= sc;
        }
        for (int kk = 0; kk < FBN; kk += 4) {
            float4 p4[4];
#pragma unroll
            for (int i = 0; i < 4; i++)
                p4[i] = *reinterpret_cast<const float4*>(
                    &S[(ty * 4 + i) * SSTRIDE + kk]);
#pragma unroll
            for (int u = 0; u < 4; u++) {
                float4 v0 = *reinterpret_cast<const float4*>(
                    &Vs[(kk + u) * QSTRIDE + tx * 8]);
                float4 v1 = *reinterpret_cast<const float4*>(
                    &Vs[(kk + u) * QSTRIDE + tx * 8 + 4]);
#pragma unroll
                for (int i = 0; i < 4; i++) {
                    float p = (u == 0) ? p4[i].x : (u == 1) ? p4[i].y
                              : (u == 2) ? p4[i].z : p4[i].w;
                    acc[i][0] += p * v0.x; acc[i][1] += p * v0.y;
                    acc[i][2] += p * v0.z; acc[i][3] += p * v0.w;
                    acc[i][4] += p * v1.x; acc[i][5] += p * v1.y;
                    acc[i][6] += p * v1.z; acc[i][7] += p * v1.w;
                }
            }
        }
        __syncthreads();
    }

    // finalize: divide by l and store
    float* ob = o + (size_t)b * LL * rs + (size_t)h * HD;
#pragma unroll
    for (int i = 0; i < 4; i++) {
        float inv = 1.f / lrow[ty * 4 + i];
        float4 o0 = make_float4(acc[i][0] * inv, acc[i][1] * inv,
                                acc[i][2] * inv, acc[i][3] * inv);
        float4 o1 = make_float4(acc[i][4] * inv, acc[i][5] * inv,
                                acc[i][6] * inv, acc[i][7] * inv);
        size_t base = (size_t)(q0 + ty * 4 + i) * rs + tx * 8;
        *reinterpret_cast<float4*>(&ob[base]) = o0;
        *reinterpret_cast<float4*>(&ob[base + 4]) = o1;
    }
}

// ---------------------------------------------------------------------------
// Confidence head: logits[row] = dot(out[row,:], Wc); conf = sigmoid(logits)
// ---------------------------------------------------------------------------
__global__ void conf_kernel(const float* __restrict__ out,
                            const float* __restrict__ Wc,
                            float* __restrict__ conf,
                            float* __restrict__ logits) {
    __shared__ float red[256];
    int row = blockIdx.x;
    const float* o = out + (size_t)row * DD;
    float s = 0.f;
    for (int i = threadIdx.x; i < DD; i += 256) s += o[i] * Wc[i];
    red[threadIdx.x] = s;
    __syncthreads();
    for (int off = 128; off > 0; off >>= 1) {
        if (threadIdx.x < off) red[threadIdx.x] += red[threadIdx.x + off];
        __syncthreads();
    }
    if (threadIdx.x == 0) {
        float lg = red[0];
        logits[row] = lg;
        conf[row] = 1.f / (1.f + expf(-lg));
    }
}

// ---------------------------------------------------------------------------
// Launch
// ---------------------------------------------------------------------------
extern "C" void kernel_launch(void* const* d_in, const int* in_sizes, int n_in,
                              void* d_out, int out_size) {
    const float* x  = (const float*)d_in[0];
    const float* Wq = (const float*)d_in[1];
    const float* Wk = (const float*)d_in[2];
    const float* Wv = (const float*)d_in[3];
    const float* Wo = (const float*)d_in[4];
    const float* Wc = (const float*)d_in[5];

    float* out    = (float*)d_out;                      // [B,L,D]
    float* conf   = out + (size_t)MROWS * DD;           // [B,L,1]
    float* logits = conf + MROWS;                       // [B,L,1]

    float *q, *k, *v, *att;
    cudaGetSymbolAddress((void**)&q,   g_q);
    cudaGetSymbolAddress((void**)&k,   g_k);
    cudaGetSymbolAddress((void**)&v,   g_v);
    cudaGetSymbolAddress((void**)&att, g_att);

    dim3 gg(DD / GBN, MROWS / GBM);   // (16, 32)
    gemm_nt_kernel<<<gg, 256>>>(x, Wq, q,   MROWS, DD, DD);
    gemm_nt_kernel<<<gg, 256>>>(x, Wk, k,   MROWS, DD, DD);
    gemm_nt_kernel<<<gg, 256>>>(x, Wv, v,   MROWS, DD, DD);

    int nrope = MROWS * HH * 64;
    rope_kernel<<<(nrope + 255) / 256, 256>>>(q);
    rope_kernel<<<(nrope + 255) / 256, 256>>>(k);

    const int fsmem =
        (3 * FBM * QSTRIDE + FBM * SSTRIDE + 3 * FBM) * (int)sizeof(float);
    cudaFuncSetAttribute(flash_kernel,
                         cudaFuncAttributeMaxDynamicSharedMemorySize, fsmem);
    flash_kernel<<<dim3(LL / FBM, HH, BB), 256, fsmem>>>(q, k, v, att);

    gemm_nt_kernel<<<gg, 256>>>(att, Wo, out, MROWS, DD, DD);

    conf_kernel<<<MROWS, 256>>>(out, Wc, conf, logits);
}

// round 5
// speedup vs baseline: 1.4229x; 1.4229x over previous
#include <cuda_runtime.h>
#include <math.h>
#include <stdint.h>

// Problem constants (fixed by the dataset)
#define BB 2
#define LL 2048
#define DD 2048
#define HH 16
#define HD 128
#define MROWS (BB * LL)   // 4096

// ---------------------------------------------------------------------------
// Scratch (no cudaMalloc allowed — __device__ globals per the rules)
// ---------------------------------------------------------------------------
__device__ float g_q[(size_t)MROWS * DD];
__device__ float g_k[(size_t)MROWS * DD];
__device__ float g_v[(size_t)MROWS * DD];
__device__ float g_att[(size_t)MROWS * DD];

// ---------------------------------------------------------------------------
// Tensor-core GEMM (tf32 mma.sync, fp32 accum):
//   C[M,N] = A[M,K] * B[N,K]^T   (row-major, K contiguous — NT GEMM)
// BM=BN=128, BK=32, 256 threads, warp grid 2x4, warp tile 64x32, m16n8k8.
// Smem natural [m][k] layout, stride 36 floats -> conflict-free frag loads
// (bank = 4*(lane>>2) + (lane&3), all 32 distinct).
// ---------------------------------------------------------------------------
#define TSA 36

__device__ __forceinline__ uint32_t f2tf32(float f) {
    uint32_t u;
    asm("cvt.rna.tf32.f32 %0, %1;" : "=r"(u) : "f"(f));
    return u;
}

__global__ __launch_bounds__(256, 2)
void gemm_tf32_nt(const float* __restrict__ A, const float* __restrict__ B,
                  float* __restrict__ C, int M, int N, int K) {
    __shared__ uint32_t As[128][TSA];
    __shared__ uint32_t Bs[128][TSA];

    const int tid  = threadIdx.x;
    const int lane = tid & 31;
    const int warp = tid >> 5;
    const int wm = warp >> 2;             // 0..1
    const int wn = warp & 3;              // 0..3
    const int g = lane >> 2;              // groupID 0..7
    const int q = lane & 3;               // thread-in-group 0..3
    const int bm = blockIdx.y * 128;
    const int bn = blockIdx.x * 128;

    const int lr = tid >> 3;              // 0..31 (row group for loads)
    const int lc = (tid & 7) * 4;         // 0,4,...,28 (col for float4 load)

    float acc[4][4][4];
#pragma unroll
    for (int mf = 0; mf < 4; mf++)
#pragma unroll
        for (int nf = 0; nf < 4; nf++)
#pragma unroll
            for (int e = 0; e < 4; e++) acc[mf][nf][e] = 0.f;

    for (int k0 = 0; k0 < K; k0 += 32) {
        // ---- gmem -> smem (tf32-converted), STS.128, conflict-free ----
#pragma unroll
        for (int h = 0; h < 4; h++) {
            int row = lr + h * 32;
            float4 va = *reinterpret_cast<const float4*>(
                &A[(size_t)(bm + row) * K + k0 + lc]);
            float4 vb = *reinterpret_cast<const float4*>(
                &B[(size_t)(bn + row) * K + k0 + lc]);
            uint4 ua = make_uint4(f2tf32(va.x), f2tf32(va.y),
                                  f2tf32(va.z), f2tf32(va.w));
            uint4 ub = make_uint4(f2tf32(vb.x), f2tf32(vb.y),
                                  f2tf32(vb.z), f2tf32(vb.w));
            *reinterpret_cast<uint4*>(&As[row][lc]) = ua;
            *reinterpret_cast<uint4*>(&Bs[row][lc]) = ub;
        }
        __syncthreads();

        // ---- 4 k-steps of m16n8k8 ----
#pragma unroll
        for (int ks = 0; ks < 4; ks++) {
            const int kq = ks * 8 + q;
            uint32_t af[4][4], bf[4][2];
#pragma unroll
            for (int mf = 0; mf < 4; mf++) {
                int r = wm * 64 + mf * 16 + g;
                af[mf][0] = As[r][kq];
                af[mf][1] = As[r + 8][kq];
                af[mf][2] = As[r][kq + 4];
                af[mf][3] = As[r + 8][kq + 4];
            }
#pragma unroll
            for (int nf = 0; nf < 4; nf++) {
                int c = wn * 32 + nf * 8 + g;
                bf[nf][0] = Bs[c][kq];
                bf[nf][1] = Bs[c][kq + 4];
            }
#pragma unroll
            for (int mf = 0; mf < 4; mf++)
#pragma unroll
                for (int nf = 0; nf < 4; nf++) {
                    asm volatile(
                        "mma.sync.aligned.m16n8k8.row.col.f32.tf32.tf32.f32 "
                        "{%0,%1,%2,%3}, {%4,%5,%6,%7}, {%8,%9}, {%0,%1,%2,%3};"
                        : "+f"(acc[mf][nf][0]), "+f"(acc[mf][nf][1]),
                          "+f"(acc[mf][nf][2]), "+f"(acc[mf][nf][3])
                        : "r"(af[mf][0]), "r"(af[mf][1]),
                          "r"(af[mf][2]), "r"(af[mf][3]),
                          "r"(bf[nf][0]), "r"(bf[nf][1]));
                }
        }
        __syncthreads();
    }

    // ---- epilogue: c0/c1 = (row g, cols 2q,2q+1); c2/c3 = row g+8 ----
#pragma unroll
    for (int mf = 0; mf < 4; mf++) {
        int r0 = bm + wm * 64 + mf * 16 + g;
#pragma unroll
        for (int nf = 0; nf < 4; nf++) {
            int c0 = bn + wn * 32 + nf * 8 + q * 2;
            *reinterpret_cast<float2*>(&C[(size_t)r0 * N + c0]) =
                make_float2(acc[mf][nf][0], acc[mf][nf][1]);
            *reinterpret_cast<float2*>(&C[(size_t)(r0 + 8) * N + c0]) =
                make_float2(acc[mf][nf][2], acc[mf][nf][3]);
        }
    }
}

// ---------------------------------------------------------------------------
// RoPE (in-place on [B*L, H, HD] tensor). One thread per (row, head, i<64).
// ---------------------------------------------------------------------------
__global__ void rope_kernel(float* __restrict__ t) {
    int idx = blockIdx.x * blockDim.x + threadIdx.x;
    const int total = MROWS * HH * 64;
    if (idx >= total) return;
    int i = idx % 64;
    int h = (idx / 64) % HH;
    int row = idx / (64 * HH);     // b*L + l
    int pos = row % LL;

    // inv_freq = 10000^(-i/64)
    const float LN10000_DIV64 = 0.14391156f;  // ln(10000)/64
    float freq = expf(-(float)i * LN10000_DIV64);
    float ang = (float)pos * freq;
    float s, c;
    sincosf(ang, &s, &c);

    float* p = t + (size_t)row * DD + h * HD;
    float a = p[i];
    float b = p[i + 64];
    p[i]      = a * c - b * s;
    p[i + 64] = b * c + a * s;
}

// ---------------------------------------------------------------------------
// Flash attention, fp32, streaming softmax. BM=BN=64, 256 threads.
// Layout: q/k/v/o are [B*L, H, HD] (row stride D=2048 floats).
// (Unchanged from the round-2 PASS kernel.)
// ---------------------------------------------------------------------------
#define FBM 64
#define FBN 64
#define QSTRIDE 132   // HD + 4 padding
#define SSTRIDE 68    // FBN + 4 padding (keeps 16B alignment)

__global__ __launch_bounds__(256, 1)
void flash_kernel(const float* __restrict__ q, const float* __restrict__ k,
                  const float* __restrict__ v, float* __restrict__ o) {
    extern __shared__ float sm[];
    float* Qs   = sm;                       // [FBM][QSTRIDE]
    float* Ks   = Qs + FBM * QSTRIDE;       // [FBN][QSTRIDE]
    float* Vs   = Ks + FBN * QSTRIDE;       // [FBN][QSTRIDE]
    float* S    = Vs + FBN * QSTRIDE;       // [FBM][SSTRIDE]
    float* mrow = S + FBM * SSTRIDE;        // [FBM]
    float* lrow = mrow + FBM;               // [FBM]
    float* srow = lrow + FBM;               // [FBM]

    const int tid = threadIdx.x;
    const int tx = tid % 16;                // 0..15
    const int ty = tid / 16;                // 0..15
    const int b = blockIdx.z;
    const int h = blockIdx.y;
    const int q0 = blockIdx.x * FBM;

    const size_t rs = (size_t)HH * HD;      // 2048
    const float* qb = q + (size_t)b * LL * rs + (size_t)h * HD;
    const float* kb = k + (size_t)b * LL * rs + (size_t)h * HD;
    const float* vb = v + (size_t)b * LL * rs + (size_t)h * HD;

    // load Q tile (64 x 128)
    for (int i = tid; i < FBM * 32; i += 256) {
        int r = i / 32, c = (i % 32) * 4;
        float4 val = *reinterpret_cast<const float4*>(
            &qb[(size_t)(q0 + r) * rs + c]);
        *reinterpret_cast<float4*>(&Qs[r * QSTRIDE + c]) = val;
    }
    if (tid < FBM) { mrow[tid] = -INFINITY; lrow[tid] = 0.f; }

    float acc[4][8];
#pragma unroll
    for (int i = 0; i < 4; i++)
#pragma unroll
        for (int j = 0; j < 8; j++) acc[i][j] = 0.f;

    __syncthreads();
    const float scale = 0.08838834764831845f;  // 1/sqrt(128)

    for (int k0 = 0; k0 < LL; k0 += FBN) {
        // load K/V tiles
        for (int i = tid; i < FBN * 32; i += 256) {
            int r = i / 32, c = (i % 32) * 4;
            *reinterpret_cast<float4*>(&Ks[r * QSTRIDE + c]) =
                *reinterpret_cast<const float4*>(&kb[(size_t)(k0 + r) * rs + c]);
            *reinterpret_cast<float4*>(&Vs[r * QSTRIDE + c]) =
                *reinterpret_cast<const float4*>(&vb[(size_t)(k0 + r) * rs + c]);
        }
        __syncthreads();

        // S = Q Kt (this thread: rows ty*4+i, cols tx*4+j)
        float sacc[4][4];
#pragma unroll
        for (int i = 0; i < 4; i++)
#pragma unroll
            for (int j = 0; j < 4; j++) sacc[i][j] = 0.f;

        for (int d = 0; d < HD; d += 4) {
            float4 q4[4], k4[4];
#pragma unroll
            for (int i = 0; i < 4; i++)
                q4[i] = *reinterpret_cast<const float4*>(
                    &Qs[(ty * 4 + i) * QSTRIDE + d]);
#pragma unroll
            for (int j = 0; j < 4; j++)
                k4[j] = *reinterpret_cast<const float4*>(
                    &Ks[(tx * 4 + j) * QSTRIDE + d]);
#pragma unroll
            for (int i = 0; i < 4; i++)
#pragma unroll
                for (int j = 0; j < 4; j++) {
                    sacc[i][j] += q4[i].x * k4[j].x;
                    sacc[i][j] += q4[i].y * k4[j].y;
                    sacc[i][j] += q4[i].z * k4[j].z;
                    sacc[i][j] += q4[i].w * k4[j].w;
                }
        }
#pragma unroll
        for (int i = 0; i < 4; i++) {
            float4 sv = make_float4(sacc[i][0] * scale, sacc[i][1] * scale,
                                    sacc[i][2] * scale, sacc[i][3] * scale);
            *reinterpret_cast<float4*>(&S[(ty * 4 + i) * SSTRIDE + tx * 4]) = sv;
        }
        __syncthreads();

        // per-row online softmax (one thread per row)
        if (tid < FBM) {
            float mold = mrow[tid];
            float mt = mold;
            float* srowp = &S[tid * SSTRIDE];
#pragma unroll 8
            for (int j = 0; j < FBN; j++) mt = fmaxf(mt, srowp[j]);
            float sc = __expf(mold - mt);
            float ls = 0.f;
#pragma unroll 8
            for (int j = 0; j < FBN; j++) {
                float p = __expf(srowp[j] - mt);
                srowp[j] = p;
                ls += p;
            }
            mrow[tid] = mt;
            lrow[tid] = lrow[tid] * sc + ls;
            srow[tid] = sc;
        }
        __syncthreads();

        // O = O*scale + P V (this thread: rows ty*4+i, cols tx*8+j)
#pragma unroll
        for (int i = 0; i < 4; i++) {
            float sc = srow[ty * 4 + i];
#pragma unroll
            for (int j = 0; j < 8; j++) acc[i][j] *= sc;
        }
        for (int kk = 0; kk < FBN; kk += 4) {
            float4 p4[4];
#pragma unroll
            for (int i = 0; i < 4; i++)
                p4[i] = *reinterpret_cast<const float4*>(
                    &S[(ty * 4 + i) * SSTRIDE + kk]);
#pragma unroll
            for (int u = 0; u < 4; u++) {
                float4 v0 = *reinterpret_cast<const float4*>(
                    &Vs[(kk + u) * QSTRIDE + tx * 8]);
                float4 v1 = *reinterpret_cast<const float4*>(
                    &Vs[(kk + u) * QSTRIDE + tx * 8 + 4]);
#pragma unroll
                for (int i = 0; i < 4; i++) {
                    float p = (u == 0) ? p4[i].x : (u == 1) ? p4[i].y
                              : (u == 2) ? p4[i].z : p4[i].w;
                    acc[i][0] += p * v0.x; acc[i][1] += p * v0.y;
                    acc[i][2] += p * v0.z; acc[i][3] += p * v0.w;
                    acc[i][4] += p * v1.x; acc[i][5] += p * v1.y;
                    acc[i][6] += p * v1.z; acc[i][7] += p * v1.w;
                }
            }
        }
        __syncthreads();
    }

    // finalize: divide by l and store
    float* ob = o + (size_t)b * LL * rs + (size_t)h * HD;
#pragma unroll
    for (int i = 0; i < 4; i++) {
        float inv = 1.f / lrow[ty * 4 + i];
        float4 o0 = make_float4(acc[i][0] * inv, acc[i][1] * inv,
                                acc[i][2] * inv, acc[i][3] * inv);
        float4 o1 = make_float4(acc[i][4] * inv, acc[i][5] * inv,
                                acc[i][6] * inv, acc[i][7] * inv);
        size_t base = (size_t)(q0 + ty * 4 + i) * rs + tx * 8;
        *reinterpret_cast<float4*>(&ob[base]) = o0;
        *reinterpret_cast<float4*>(&ob[base + 4]) = o1;
    }
}

// ---------------------------------------------------------------------------
// Confidence head: logits[row] = dot(out[row,:], Wc); conf = sigmoid(logits)
// ---------------------------------------------------------------------------
__global__ void conf_kernel(const float* __restrict__ out,
                            const float* __restrict__ Wc,
                            float* __restrict__ conf,
                            float* __restrict__ logits) {
    __shared__ float red[256];
    int row = blockIdx.x;
    const float* o = out + (size_t)row * DD;
    float s = 0.f;
    for (int i = threadIdx.x; i < DD; i += 256) s += o[i] * Wc[i];
    red[threadIdx.x] = s;
    __syncthreads();
    for (int off = 128; off > 0; off >>= 1) {
        if (threadIdx.x < off) red[threadIdx.x] += red[threadIdx.x + off];
        __syncthreads();
    }
    if (threadIdx.x == 0) {
        float lg = red[0];
        logits[row] = lg;
        conf[row] = 1.f / (1.f + expf(-lg));
    }
}

// ---------------------------------------------------------------------------
// Launch
// ---------------------------------------------------------------------------
extern "C" void kernel_launch(void* const* d_in, const int* in_sizes, int n_in,
                              void* d_out, int out_size) {
    const float* x  = (const float*)d_in[0];
    const float* Wq = (const float*)d_in[1];
    const float* Wk = (const float*)d_in[2];
    const float* Wv = (const float*)d_in[3];
    const float* Wo = (const float*)d_in[4];
    const float* Wc = (const float*)d_in[5];

    float* out    = (float*)d_out;                      // [B,L,D]
    float* conf   = out + (size_t)MROWS * DD;           // [B,L,1]
    float* logits = conf + MROWS;                       // [B,L,1]

    float *q, *k, *v, *att;
    cudaGetSymbolAddress((void**)&q,   g_q);
    cudaGetSymbolAddress((void**)&k,   g_k);
    cudaGetSymbolAddress((void**)&v,   g_v);
    cudaGetSymbolAddress((void**)&att, g_att);

    dim3 gg(DD / 128, MROWS / 128);   // (16, 32)
    gemm_tf32_nt<<<gg, 256>>>(x, Wq, q,   MROWS, DD, DD);
    gemm_tf32_nt<<<gg, 256>>>(x, Wk, k,   MROWS, DD, DD);
    gemm_tf32_nt<<<gg, 256>>>(x, Wv, v,   MROWS, DD, DD);

    int nrope = MROWS * HH * 64;
    rope_kernel<<<(nrope + 255) / 256, 256>>>(q);
    rope_kernel<<<(nrope + 255) / 256, 256>>>(k);

    const int fsmem =
        (3 * FBM * QSTRIDE + FBM * SSTRIDE + 3 * FBM) * (int)sizeof(float);
    cudaFuncSetAttribute(flash_kernel,
                         cudaFuncAttributeMaxDynamicSharedMemorySize, fsmem);
    flash_kernel<<<dim3(LL / FBM, HH, BB), 256, fsmem>>>(q, k, v, att);

    gemm_tf32_nt<<<gg, 256>>>(att, Wo, out, MROWS, DD, DD);

    conf_kernel<<<MROWS, 256>>>(out, Wc, conf, logits);
}

// round 6
// speedup vs baseline: 2.3395x; 1.6441x over previous
#include <cuda_runtime.h>
#include <math.h>
#include <stdint.h>

// Problem constants (fixed by the dataset)
#define BB 2
#define LL 2048
#define DD 2048
#define HH 16
#define HD 128
#define MROWS (BB * LL)   // 4096

// ---------------------------------------------------------------------------
// Scratch (no cudaMalloc allowed — __device__ globals per the rules)
// ---------------------------------------------------------------------------
__device__ float g_q[(size_t)MROWS * DD];
__device__ float g_k[(size_t)MROWS * DD];
__device__ float g_v[(size_t)MROWS * DD];
__device__ float g_att[(size_t)MROWS * DD];

// ---------------------------------------------------------------------------
// tf32 helpers
// ---------------------------------------------------------------------------
__device__ __forceinline__ uint32_t f2tf32(float f) {
    uint32_t u;
    asm("cvt.rna.tf32.f32 %0, %1;" : "=r"(u) : "f"(f));
    return u;
}

__device__ __forceinline__ void split_tf32(float x, uint32_t& hi, uint32_t& lo) {
    hi = f2tf32(x);
    lo = f2tf32(x - __uint_as_float(hi));
}

__device__ __forceinline__ void mma_tf32(float c[4],
                                         uint32_t a0, uint32_t a1,
                                         uint32_t a2, uint32_t a3,
                                         uint32_t b0, uint32_t b1) {
    asm volatile(
        "mma.sync.aligned.m16n8k8.row.col.f32.tf32.tf32.f32 "
        "{%0,%1,%2,%3}, {%4,%5,%6,%7}, {%8,%9}, {%0,%1,%2,%3};"
        : "+f"(c[0]), "+f"(c[1]), "+f"(c[2]), "+f"(c[3])
        : "r"(a0), "r"(a1), "r"(a2), "r"(a3), "r"(b0), "r"(b1));
}

// ---------------------------------------------------------------------------
// Tensor-core GEMM (plain tf32 mma.sync, fp32 accum) — validated in round 5.
//   C[M,N] = A[M,K] * B[N,K]^T
// ---------------------------------------------------------------------------
#define TSA 36

__global__ __launch_bounds__(256, 2)
void gemm_tf32_nt(const float* __restrict__ A, const float* __restrict__ B,
                  float* __restrict__ C, int M, int N, int K) {
    __shared__ uint32_t As[128][TSA];
    __shared__ uint32_t Bs[128][TSA];

    const int tid  = threadIdx.x;
    const int lane = tid & 31;
    const int warp = tid >> 5;
    const int wm = warp >> 2;             // 0..1
    const int wn = warp & 3;              // 0..3
    const int g = lane >> 2;              // groupID 0..7
    const int q = lane & 3;               // thread-in-group 0..3
    const int bm = blockIdx.y * 128;
    const int bn = blockIdx.x * 128;

    const int lr = tid >> 3;              // 0..31
    const int lc = (tid & 7) * 4;         // 0,4,...,28

    float acc[4][4][4];
#pragma unroll
    for (int mf = 0; mf < 4; mf++)
#pragma unroll
        for (int nf = 0; nf < 4; nf++)
#pragma unroll
            for (int e = 0; e < 4; e++) acc[mf][nf][e] = 0.f;

    for (int k0 = 0; k0 < K; k0 += 32) {
#pragma unroll
        for (int h = 0; h < 4; h++) {
            int row = lr + h * 32;
            float4 va = *reinterpret_cast<const float4*>(
                &A[(size_t)(bm + row) * K + k0 + lc]);
            float4 vb = *reinterpret_cast<const float4*>(
                &B[(size_t)(bn + row) * K + k0 + lc]);
            uint4 ua = make_uint4(f2tf32(va.x), f2tf32(va.y),
                                  f2tf32(va.z), f2tf32(va.w));
            uint4 ub = make_uint4(f2tf32(vb.x), f2tf32(vb.y),
                                  f2tf32(vb.z), f2tf32(vb.w));
            *reinterpret_cast<uint4*>(&As[row][lc]) = ua;
            *reinterpret_cast<uint4*>(&Bs[row][lc]) = ub;
        }
        __syncthreads();

#pragma unroll
        for (int ks = 0; ks < 4; ks++) {
            const int kq = ks * 8 + q;
            uint32_t af[4][4], bf[4][2];
#pragma unroll
            for (int mf = 0; mf < 4; mf++) {
                int r = wm * 64 + mf * 16 + g;
                af[mf][0] = As[r][kq];
                af[mf][1] = As[r + 8][kq];
                af[mf][2] = As[r][kq + 4];
                af[mf][3] = As[r + 8][kq + 4];
            }
#pragma unroll
            for (int nf = 0; nf < 4; nf++) {
                int c = wn * 32 + nf * 8 + g;
                bf[nf][0] = Bs[c][kq];
                bf[nf][1] = Bs[c][kq + 4];
            }
#pragma unroll
            for (int mf = 0; mf < 4; mf++)
#pragma unroll
                for (int nf = 0; nf < 4; nf++)
                    mma_tf32(acc[mf][nf], af[mf][0], af[mf][1],
                             af[mf][2], af[mf][3], bf[nf][0], bf[nf][1]);
        }
        __syncthreads();
    }

#pragma unroll
    for (int mf = 0; mf < 4; mf++) {
        int r0 = bm + wm * 64 + mf * 16 + g;
#pragma unroll
        for (int nf = 0; nf < 4; nf++) {
            int c0 = bn + wn * 32 + nf * 8 + q * 2;
            *reinterpret_cast<float2*>(&C[(size_t)r0 * N + c0]) =
                make_float2(acc[mf][nf][0], acc[mf][nf][1]);
            *reinterpret_cast<float2*>(&C[(size_t)(r0 + 8) * N + c0]) =
                make_float2(acc[mf][nf][2], acc[mf][nf][3]);
        }
    }
}

// ---------------------------------------------------------------------------
// RoPE (in-place on [B*L, H, HD] tensor).
// ---------------------------------------------------------------------------
__global__ void rope_kernel(float* __restrict__ t) {
    int idx = blockIdx.x * blockDim.x + threadIdx.x;
    const int total = MROWS * HH * 64;
    if (idx >= total) return;
    int i = idx % 64;
    int h = (idx / 64) % HH;
    int row = idx / (64 * HH);
    int pos = row % LL;

    const float LN10000_DIV64 = 0.14391156f;
    float freq = expf(-(float)i * LN10000_DIV64);
    float ang = (float)pos * freq;
    float s, c;
    sincosf(ang, &s, &c);

    float* p = t + (size_t)row * DD + h * HD;
    float a = p[i];
    float b = p[i + 64];
    p[i]      = a * c - b * s;
    p[i + 64] = b * c + a * s;
}

// ---------------------------------------------------------------------------
// Flash attention with tensor cores (split-tf32 = 3-mma fp32 emulation).
// BM=BN=64, HD=128. 256 threads = 8 warps, warp grid 4(m) x 2(n).
// S phase: warp tile 16x32 (4 nfrags, 16 ks). PV phase: 16x64 (8 nfrags, 8 ks).
// Smem strides: Q/K 132 (bank=4g+q), V 136 (bank=8q+g), S 68 (bank=4g+q) —
// all conflict-free for the m16n8k8 fragment access patterns.
// ---------------------------------------------------------------------------
#define FQS 132
#define FVS 136
#define FSS 68
#define FLASH_SMEM ((64*FQS*2 + 64*FVS + 64*FSS + 192) * 4)

__global__ __launch_bounds__(256, 1)
void flash_tc_kernel(const float* __restrict__ qp, const float* __restrict__ kp,
                     const float* __restrict__ vp, float* __restrict__ op) {
    extern __shared__ float sm[];
    float* Qs   = sm;                     // [64][FQS]  (pre-scaled by 1/sqrt(hd))
    float* Ks   = Qs + 64 * FQS;          // [64][FQS]
    float* Vs   = Ks + 64 * FQS;          // [64][FVS]
    float* Ss   = Vs + 64 * FVS;          // [64][FSS]
    float* mrow = Ss + 64 * FSS;          // [64]
    float* lrow = mrow + 64;              // [64]
    float* srow = lrow + 64;              // [64]

    const int tid  = threadIdx.x;
    const int lane = tid & 31;
    const int warp = tid >> 5;
    const int wm = warp >> 1;             // 0..3  (16-row block)
    const int wn = warp & 1;              // 0..1
    const int g  = lane >> 2;             // 0..7
    const int qt = lane & 3;              // 0..3

    const int b  = blockIdx.z;
    const int h  = blockIdx.y;
    const int q0 = blockIdx.x * 64;

    const size_t rs = (size_t)HH * HD;    // 2048
    const float* qb = qp + (size_t)b * LL * rs + (size_t)h * HD;
    const float* kb = kp + (size_t)b * LL * rs + (size_t)h * HD;
    const float* vb = vp + (size_t)b * LL * rs + (size_t)h * HD;
    float*       ob = op + (size_t)b * LL * rs + (size_t)h * HD;

    const float scale = 0.08838834764831845f;  // 1/sqrt(128)

    // load Q tile (64 x 128), pre-scaled
    for (int i = tid; i < 64 * 32; i += 256) {
        int r = i >> 5, c = (i & 31) * 4;
        float4 val = *reinterpret_cast<const float4*>(&qb[(size_t)(q0 + r) * rs + c]);
        val.x *= scale; val.y *= scale; val.z *= scale; val.w *= scale;
        *reinterpret_cast<float4*>(&Qs[r * FQS + c]) = val;
    }
    if (tid < 64) { mrow[tid] = -INFINITY; lrow[tid] = 0.f; }

    float oacc[8][4];
#pragma unroll
    for (int nf = 0; nf < 8; nf++)
#pragma unroll
        for (int e = 0; e < 4; e++) oacc[nf][e] = 0.f;

    __syncthreads();

    const int rA  = 16 * wm + g;          // fragment row (and +8)
    for (int k0 = 0; k0 < LL; k0 += 64) {
        // ---- load K/V tiles ----
        for (int i = tid; i < 64 * 32; i += 256) {
            int r = i >> 5, c = (i & 31) * 4;
            *reinterpret_cast<float4*>(&Ks[r * FQS + c]) =
                *reinterpret_cast<const float4*>(&kb[(size_t)(k0 + r) * rs + c]);
            *reinterpret_cast<float4*>(&Vs[r * FVS + c]) =
                *reinterpret_cast<const float4*>(&vb[(size_t)(k0 + r) * rs + c]);
        }
        __syncthreads();

        // ---- S = Q K^T (split-tf32, 3 mma per frag pair) ----
        float sacc[4][4];
#pragma unroll
        for (int nf = 0; nf < 4; nf++)
#pragma unroll
            for (int e = 0; e < 4; e++) sacc[nf][e] = 0.f;

#pragma unroll
        for (int ks = 0; ks < 16; ks++) {
            const int kq = ks * 8 + qt;
            float a0 = Qs[rA * FQS + kq];
            float a1 = Qs[(rA + 8) * FQS + kq];
            float a2 = Qs[rA * FQS + kq + 4];
            float a3 = Qs[(rA + 8) * FQS + kq + 4];
            uint32_t ah[4], al[4];
            split_tf32(a0, ah[0], al[0]);
            split_tf32(a1, ah[1], al[1]);
            split_tf32(a2, ah[2], al[2]);
            split_tf32(a3, ah[3], al[3]);
#pragma unroll
            for (int nf = 0; nf < 4; nf++) {
                int c = 32 * wn + 8 * nf + g;
                float b0 = Ks[c * FQS + kq];
                float b1 = Ks[c * FQS + kq + 4];
                uint32_t bh0, bl0, bh1, bl1;
                split_tf32(b0, bh0, bl0);
                split_tf32(b1, bh1, bl1);
                mma_tf32(sacc[nf], ah[0], ah[1], ah[2], ah[3], bl0, bl1);
                mma_tf32(sacc[nf], al[0], al[1], al[2], al[3], bh0, bh1);
                mma_tf32(sacc[nf], ah[0], ah[1], ah[2], ah[3], bh0, bh1);
            }
        }

        // ---- store S tile to smem ----
#pragma unroll
        for (int nf = 0; nf < 4; nf++) {
            int col = 32 * wn + 8 * nf + 2 * qt;
            *reinterpret_cast<float2*>(&Ss[rA * FSS + col]) =
                make_float2(sacc[nf][0], sacc[nf][1]);
            *reinterpret_cast<float2*>(&Ss[(rA + 8) * FSS + col]) =
                make_float2(sacc[nf][2], sacc[nf][3]);
        }
        __syncthreads();

        // ---- online softmax: 4 threads per row, 16 cols each ----
        {
            int row = tid >> 2, qq = tid & 3;
            float* sp = &Ss[row * FSS + qq * 16];
            float mold = mrow[row];
            float mt = mold;
#pragma unroll
            for (int j = 0; j < 16; j++) mt = fmaxf(mt, sp[j]);
            mt = fmaxf(mt, __shfl_xor_sync(0xffffffffu, mt, 1));
            mt = fmaxf(mt, __shfl_xor_sync(0xffffffffu, mt, 2));
            float ls = 0.f;
#pragma unroll
            for (int j = 0; j < 16; j++) {
                float p = __expf(sp[j] - mt);
                sp[j] = p;
                ls += p;
            }
            ls += __shfl_xor_sync(0xffffffffu, ls, 1);
            ls += __shfl_xor_sync(0xffffffffu, ls, 2);
            if (qq == 0) {
                float sc = __expf(mold - mt);
                mrow[row] = mt;
                lrow[row] = lrow[row] * sc + ls;
                srow[row] = sc;
            }
        }
        __syncthreads();

        // ---- rescale O accumulators ----
        {
            float scg  = srow[rA];
            float scg8 = srow[rA + 8];
#pragma unroll
            for (int nf = 0; nf < 8; nf++) {
                oacc[nf][0] *= scg;  oacc[nf][1] *= scg;
                oacc[nf][2] *= scg8; oacc[nf][3] *= scg8;
            }
        }

        // ---- O += P V (split-tf32) ----
#pragma unroll
        for (int ks = 0; ks < 8; ks++) {
            const int kq = ks * 8 + qt;
            float a0 = Ss[rA * FSS + kq];
            float a1 = Ss[(rA + 8) * FSS + kq];
            float a2 = Ss[rA * FSS + kq + 4];
            float a3 = Ss[(rA + 8) * FSS + kq + 4];
            uint32_t ah[4], al[4];
            split_tf32(a0, ah[0], al[0]);
            split_tf32(a1, ah[1], al[1]);
            split_tf32(a2, ah[2], al[2]);
            split_tf32(a3, ah[3], al[3]);
#pragma unroll
            for (int nf = 0; nf < 8; nf++) {
                int c = 64 * wn + 8 * nf + g;
                float b0 = Vs[kq * FVS + c];
                float b1 = Vs[(kq + 4) * FVS + c];
                uint32_t bh0, bl0, bh1, bl1;
                split_tf32(b0, bh0, bl0);
                split_tf32(b1, bh1, bl1);
                mma_tf32(oacc[nf], ah[0], ah[1], ah[2], ah[3], bl0, bl1);
                mma_tf32(oacc[nf], al[0], al[1], al[2], al[3], bh0, bh1);
                mma_tf32(oacc[nf], ah[0], ah[1], ah[2], ah[3], bh0, bh1);
            }
        }
        __syncthreads();   // protect Ks/Vs/Ss before next iteration overwrites
    }

    // ---- finalize: divide by l, store O ----
    {
        float invg  = 1.f / lrow[rA];
        float invg8 = 1.f / lrow[rA + 8];
#pragma unroll
        for (int nf = 0; nf < 8; nf++) {
            int col = 64 * wn + 8 * nf + 2 * qt;
            size_t r0 = (size_t)(q0 + rA) * rs + col;
            size_t r8 = (size_t)(q0 + rA + 8) * rs + col;
            *reinterpret_cast<float2*>(&ob[r0]) =
                make_float2(oacc[nf][0] * invg, oacc[nf][1] * invg);
            *reinterpret_cast<float2*>(&ob[r8]) =
                make_float2(oacc[nf][2] * invg8, oacc[nf][3] * invg8);
        }
    }
}

// ---------------------------------------------------------------------------
// Confidence head
// ---------------------------------------------------------------------------
__global__ void conf_kernel(const float* __restrict__ out,
                            const float* __restrict__ Wc,
                            float* __restrict__ conf,
                            float* __restrict__ logits) {
    __shared__ float red[256];
    int row = blockIdx.x;
    const float* o = out + (size_t)row * DD;
    float s = 0.f;
    for (int i = threadIdx.x; i < DD; i += 256) s += o[i] * Wc[i];
    red[threadIdx.x] = s;
    __syncthreads();
    for (int off = 128; off > 0; off >>= 1) {
        if (threadIdx.x < off) red[threadIdx.x] += red[threadIdx.x + off];
        __syncthreads();
    }
    if (threadIdx.x == 0) {
        float lg = red[0];
        logits[row] = lg;
        conf[row] = 1.f / (1.f + expf(-lg));
    }
}

// ---------------------------------------------------------------------------
// Launch
// ---------------------------------------------------------------------------
extern "C" void kernel_launch(void* const* d_in, const int* in_sizes, int n_in,
                              void* d_out, int out_size) {
    const float* x  = (const float*)d_in[0];
    const float* Wq = (const float*)d_in[1];
    const float* Wk = (const float*)d_in[2];
    const float* Wv = (const float*)d_in[3];
    const float* Wo = (const float*)d_in[4];
    const float* Wc = (const float*)d_in[5];

    float* out    = (float*)d_out;                      // [B,L,D]
    float* conf   = out + (size_t)MROWS * DD;           // [B,L,1]
    float* logits = conf + MROWS;                       // [B,L,1]

    float *q, *k, *v, *att;
    cudaGetSymbolAddress((void**)&q,   g_q);
    cudaGetSymbolAddress((void**)&k,   g_k);
    cudaGetSymbolAddress((void**)&v,   g_v);
    cudaGetSymbolAddress((void**)&att, g_att);

    dim3 gg(DD / 128, MROWS / 128);   // (16, 32)
    gemm_tf32_nt<<<gg, 256>>>(x, Wq, q,   MROWS, DD, DD);
    gemm_tf32_nt<<<gg, 256>>>(x, Wk, k,   MROWS, DD, DD);
    gemm_tf32_nt<<<gg, 256>>>(x, Wv, v,   MROWS, DD, DD);

    int nrope = MROWS * HH * 64;
    rope_kernel<<<(nrope + 255) / 256, 256>>>(q);
    rope_kernel<<<(nrope + 255) / 256, 256>>>(k);

    cudaFuncSetAttribute(flash_tc_kernel,
                         cudaFuncAttributeMaxDynamicSharedMemorySize, FLASH_SMEM);
    flash_tc_kernel<<<dim3(LL / 64, HH, BB), 256, FLASH_SMEM>>>(q, k, v, att);

    gemm_tf32_nt<<<gg, 256>>>(att, Wo, out, MROWS, DD, DD);

    conf_kernel<<<MROWS, 256>>>(out, Wc, conf, logits);
}